// round 16
// baseline (speedup 1.0000x reference)
#include <cuda_runtime.h>
#include <cstdint>

// Embedding gather via the bulk-async copy engine (UBLKCP), bypassing the
// LSU/register path entirely:
//   per row: cp.async.bulk GMEM->SMEM (4 KB, evict_last: hot w rows stay
//   L2-resident across graph replays), then cp.async.bulk SMEM->GMEM
//   (evict_first: streaming write, closest bulk analog of st.global.cs).
// 2048 blocks x 32 threads; thread 0 drives 8 rows/block with 8 SMEM stages
// (no buffer reuse -> no ring hazards). x: [16384] i32, w: [50257,1024] f32,
// out: [16384,1024] f32.

#define ROW_BYTES 4096
#define ROWS_PER_BLOCK 8
#define STAGES 8

__device__ __forceinline__ uint32_t smem_u32(const void* p) {
    uint32_t a;
    asm("{ .reg .u64 t; cvta.to.shared.u64 t, %1; cvt.u32.u64 %0, t; }"
        : "=r"(a) : "l"(p));
    return a;
}

__global__ void __launch_bounds__(32) emb_bulk_kernel(
    const int* __restrict__ x,
    const char* __restrict__ w,
    char* __restrict__ out,
    int n_rows)
{
    __shared__ alignas(128) char buf[STAGES][ROW_BYTES];
    __shared__ alignas(8) uint64_t mbar[STAGES];

    if (threadIdx.x != 0) return;   // single-thread driver (bulk ops are single-thread)

    uint32_t mb[STAGES];
    #pragma unroll
    for (int s = 0; s < STAGES; s++) {
        mb[s] = smem_u32(&mbar[s]);
        asm volatile("mbarrier.init.shared.b64 [%0], 1;" :: "r"(mb[s]) : "memory");
    }
    asm volatile("fence.proxy.async.shared::cta;" ::: "memory");

    uint64_t pol_r, pol_w;
    asm("createpolicy.fractional.L2::evict_last.b64 %0, 1.0;"  : "=l"(pol_r));
    asm("createpolicy.fractional.L2::evict_first.b64 %0, 1.0;" : "=l"(pol_w));

    int row0 = blockIdx.x * ROWS_PER_BLOCK;
    int nbytes = ROW_BYTES;

    // Phase 1: issue all 8 gather loads (async, 32 KB in flight per CTA)
    #pragma unroll
    for (int i = 0; i < ROWS_PER_BLOCK; i++) {
        int idx = __ldg(x + row0 + i);
        uint32_t sa = smem_u32(&buf[i][0]);
        asm volatile("mbarrier.arrive.expect_tx.shared.b64 _, [%0], %1;"
                     :: "r"(mb[i]), "r"(nbytes) : "memory");
        asm volatile(
            "cp.async.bulk.shared::cta.global.mbarrier::complete_tx::bytes.L2::cache_hint"
            " [%0], [%1], %2, [%3], %4;"
            :: "r"(sa), "l"(w + (size_t)idx * ROW_BYTES), "r"(nbytes),
               "r"(mb[i]), "l"(pol_r)
            : "memory");
    }

    // Phase 2: as each load lands, bulk-store the row out (streaming)
    #pragma unroll
    for (int i = 0; i < ROWS_PER_BLOCK; i++) {
        // wait mbarrier phase 0 (each barrier completes exactly once)
        asm volatile(
            "{\n\t"
            ".reg .pred P;\n\t"
            "WAIT_%=:\n\t"
            "mbarrier.try_wait.parity.acquire.cta.shared::cta.b64 P, [%0], 0, 0x989680;\n\t"
            "@P bra.uni DONE_%=;\n\t"
            "bra.uni WAIT_%=;\n\t"
            "DONE_%=:\n\t"
            "}"
            :: "r"(mb[i]) : "memory");

        uint32_t sa = smem_u32(&buf[i][0]);
        asm volatile(
            "cp.async.bulk.global.shared::cta.bulk_group.L2::cache_hint"
            " [%0], [%1], %2, %3;"
            :: "l"(out + (size_t)(row0 + i) * ROW_BYTES), "r"(sa), "r"(nbytes),
               "l"(pol_w)
            : "memory");
    }
    asm volatile("cp.async.bulk.commit_group;" ::: "memory");
    asm volatile("cp.async.bulk.wait_group 0;" ::: "memory");
}

extern "C" void kernel_launch(void* const* d_in, const int* in_sizes, int n_in,
                              void* d_out, int out_size) {
    const int*  x = (const int*)d_in[0];       // [16384] indices
    const char* w = (const char*)d_in[1];      // [50257*1024] fp32 rows (4 KB each)
    char*       o = (char*)d_out;

    int n_rows = in_sizes[0];                  // 16384
    int n_blocks = n_rows / ROWS_PER_BLOCK;    // 2048
    emb_bulk_kernel<<<n_blocks, 32>>>(x, w, o, n_rows);
}